// round 2
// baseline (speedup 1.0000x reference)
#include <cuda_runtime.h>
#include <math.h>

// Problem: x [256, 64, 2048] fp32.
//   xm  = max(x, axis=1)            -> [256, 2048]
//   gate = softmax(xm, axis=-1)     (SSA groups=1 full-rank reconstruction is identity)
//   out = gate[:, None, :] * x
//
// Pure HBM-bound: ~388 MB traffic total.

#define B 256
#define H 64
#define N 2048

__device__ float g_gate[B * N];  // 2 MB scratch (no allocs allowed)

// --- Kernel 1: per-batch max over H, then softmax over N, write gate ---
__global__ __launch_bounds__(1024, 2)
void max_softmax_kernel(const float* __restrict__ x, float* __restrict__ gate) {
    const int b = blockIdx.x;
    const int t = threadIdx.x;        // 0..1023, each owns 2 consecutive n
    const int lane = t & 31;
    const int wid  = t >> 5;

    const float* xb = x + (size_t)b * H * N;
    const int n0 = t * 2;

    float2 mx = make_float2(-INFINITY, -INFINITY);
    #pragma unroll 8
    for (int h = 0; h < H; ++h) {
        float2 v = *reinterpret_cast<const float2*>(xb + (size_t)h * N + n0);
        mx.x = fmaxf(mx.x, v.x);
        mx.y = fmaxf(mx.y, v.y);
    }

    __shared__ float sred[32];
    __shared__ float s_gmax, s_gsum;

    // ---- block max over all 2048 values ----
    float tm = fmaxf(mx.x, mx.y);
    #pragma unroll
    for (int o = 16; o > 0; o >>= 1)
        tm = fmaxf(tm, __shfl_xor_sync(0xffffffffu, tm, o));
    if (lane == 0) sred[wid] = tm;
    __syncthreads();
    if (wid == 0) {
        float v = sred[lane];
        #pragma unroll
        for (int o = 16; o > 0; o >>= 1)
            v = fmaxf(v, __shfl_xor_sync(0xffffffffu, v, o));
        if (lane == 0) s_gmax = v;
    }
    __syncthreads();
    const float gmax = s_gmax;

    // ---- exp and block sum ----
    float2 e;
    e.x = expf(mx.x - gmax);
    e.y = expf(mx.y - gmax);
    float ts = e.x + e.y;
    #pragma unroll
    for (int o = 16; o > 0; o >>= 1)
        ts += __shfl_xor_sync(0xffffffffu, ts, o);
    if (lane == 0) sred[wid] = ts;
    __syncthreads();
    if (wid == 0) {
        float v = sred[lane];
        #pragma unroll
        for (int o = 16; o > 0; o >>= 1)
            v += __shfl_xor_sync(0xffffffffu, v, o);
        if (lane == 0) s_gsum = v;
    }
    __syncthreads();
    const float inv = 1.0f / s_gsum;

    float2 g = make_float2(e.x * inv, e.y * inv);
    *reinterpret_cast<float2*>(gate + (size_t)b * N + n0) = g;
}

// --- Kernel 2: out = gate[b, n] * x[b, h, n], float4 elementwise ---
__global__ __launch_bounds__(256)
void scale_kernel(const float* __restrict__ x, const float* __restrict__ gate,
                  float* __restrict__ out) {
    // total elements = 256*64*2048 = 2^25; float4 count = 2^23
    const long long i4 = (long long)blockIdx.x * blockDim.x + threadIdx.x;
    const long long e  = i4 << 2;               // element index
    const long long b  = e >> 17;               // / (64*2048)
    const int       n  = (int)(e & (N - 1));    // within row

    float4 v = *reinterpret_cast<const float4*>(x + e);
    float4 g = *reinterpret_cast<const float4*>(gate + (b << 11) + n);
    v.x *= g.x; v.y *= g.y; v.z *= g.z; v.w *= g.w;
    *reinterpret_cast<float4*>(out + e) = v;
}

extern "C" void kernel_launch(void* const* d_in, const int* in_sizes, int n_in,
                              void* d_out, int out_size) {
    const float* x = (const float*)d_in[0];
    float* out = (float*)d_out;

    float* gate;
    cudaGetSymbolAddress((void**)&gate, g_gate);

    max_softmax_kernel<<<B, 1024>>>(x, gate);

    const long long n4 = (long long)B * H * N / 4;   // 8388608
    const int threads = 256;
    const int blocks = (int)(n4 / threads);          // 32768
    scale_kernel<<<blocks, threads>>>(x, gate, out);
}

// round 3
// speedup vs baseline: 1.0319x; 1.0319x over previous
#include <cuda_runtime.h>
#include <math.h>

// x [256, 64, 2048] fp32.
//   xm   = max(x, axis=1)
//   gate = softmax(xm, axis=-1)     (SSA groups=1 full-rank reconstruction == identity)
//   out  = gate[:, None, :] * x
//
// Fully fused: one block per batch. Phase A streams the 512 KB slab for the
// max (filling L2), softmax entirely in registers/smem, phase B re-reads the
// slab (mostly L2 hits, __ldcs evict-first) and streams out with __stcs.

#define B 256
#define H 64
#define N 2048

__global__ __launch_bounds__(512, 3)
void fused_ssa_gate_kernel(const float* __restrict__ x, float* __restrict__ out) {
    const int b    = blockIdx.x;
    const int t    = threadIdx.x;       // 512 threads, each owns 4 consecutive n
    const int lane = t & 31;
    const int wid  = t >> 5;            // 16 warps

    const float* xb = x   + (size_t)b * (H * N);
    float*       ob = out + (size_t)b * (H * N);
    const int n0 = t * 4;

    // ---- Phase A: max over H ----
    float4 mx = make_float4(-INFINITY, -INFINITY, -INFINITY, -INFINITY);
    #pragma unroll 4
    for (int h = 0; h < H; ++h) {
        float4 v = *reinterpret_cast<const float4*>(xb + h * N + n0);
        mx.x = fmaxf(mx.x, v.x);
        mx.y = fmaxf(mx.y, v.y);
        mx.z = fmaxf(mx.z, v.z);
        mx.w = fmaxf(mx.w, v.w);
    }

    __shared__ float sred[16];
    __shared__ float s_gmax, s_gsum;

    // ---- block max over all 2048 xm values ----
    float tm = fmaxf(fmaxf(mx.x, mx.y), fmaxf(mx.z, mx.w));
    #pragma unroll
    for (int o = 16; o > 0; o >>= 1)
        tm = fmaxf(tm, __shfl_xor_sync(0xffffffffu, tm, o));
    if (lane == 0) sred[wid] = tm;
    __syncthreads();
    if (wid == 0) {
        float v = (lane < 16) ? sred[lane] : -INFINITY;
        #pragma unroll
        for (int o = 8; o > 0; o >>= 1)
            v = fmaxf(v, __shfl_xor_sync(0xffffffffu, v, o));
        if (lane == 0) s_gmax = v;
    }
    __syncthreads();
    const float gmax = s_gmax;

    // ---- exp + block sum ----
    float4 e;
    e.x = expf(mx.x - gmax);
    e.y = expf(mx.y - gmax);
    e.z = expf(mx.z - gmax);
    e.w = expf(mx.w - gmax);
    float ts = (e.x + e.y) + (e.z + e.w);
    #pragma unroll
    for (int o = 16; o > 0; o >>= 1)
        ts += __shfl_xor_sync(0xffffffffu, ts, o);
    if (lane == 0) sred[wid] = ts;
    __syncthreads();
    if (wid == 0) {
        float v = (lane < 16) ? sred[lane] : 0.0f;
        #pragma unroll
        for (int o = 8; o > 0; o >>= 1)
            v += __shfl_xor_sync(0xffffffffu, v, o);
        if (lane == 0) s_gsum = v;
    }
    __syncthreads();
    const float inv = 1.0f / s_gsum;

    const float4 g = make_float4(e.x * inv, e.y * inv, e.z * inv, e.w * inv);

    // ---- Phase B: out = gate * x  (x re-read from L2; streaming hints) ----
    #pragma unroll 4
    for (int h = 0; h < H; ++h) {
        float4 v = __ldcs(reinterpret_cast<const float4*>(xb + h * N + n0));
        v.x *= g.x; v.y *= g.y; v.z *= g.z; v.w *= g.w;
        __stcs(reinterpret_cast<float4*>(ob + h * N + n0), v);
    }
}

extern "C" void kernel_launch(void* const* d_in, const int* in_sizes, int n_in,
                              void* d_out, int out_size) {
    const float* x = (const float*)d_in[0];
    float* out = (float*)d_out;
    fused_ssa_gate_kernel<<<B, 512>>>(x, out);
}

// round 5
// speedup vs baseline: 1.0981x; 1.0642x over previous
#include <cuda_runtime.h>
#include <cooperative_groups.h>
#include <math.h>

namespace cg = cooperative_groups;

// x [256, 64, 2048] fp32.
//   xm   = max(x, axis=1); gate = softmax(xm, -1)   (SSA groups=1 == identity)
//   out  = gate[:, None, :] * x
//
// One cluster of 8 CTAs per batch. Each CTA caches its [64, 256] chunk (64 KB)
// in SMEM during the max pass, softmax scalars combined via DSMEM mailboxes,
// then the scale pass reads from SMEM. DRAM traffic = 128 MB read + 128 MB
// write exactly.
//
// R4 fix: final cluster.sync() before exit — peers read each other's SMEM
// mailboxes after the last sync, so no CTA may retire until all are done.

#define B  256
#define H  64
#define N  2048
#define CLUSTER 8
#define NCH (N / CLUSTER)      // 256 cols per CTA
#define THREADS 256

// dynamic smem layout (floats)
#define OFF_XS    0                       // H*NCH = 16384
#define OFF_PMAX  (H * NCH)               // 4*NCH = 1024
#define OFF_GATE  (OFF_PMAX + 4 * NCH)    // 256
#define OFF_RED   (OFF_GATE + NCH)        // 8
#define OFF_BC    (OFF_RED + 8)           // 2
#define OFF_MBOX  (OFF_BC + 2)            // 2
#define SMEM_FLOATS (OFF_MBOX + 2)
#define SMEM_BYTES (SMEM_FLOATS * 4)

__global__ void __cluster_dims__(CLUSTER, 1, 1) __launch_bounds__(THREADS, 3)
fused_cluster_kernel(const float* __restrict__ x, float* __restrict__ out) {
    extern __shared__ float smem[];
    float* x_s    = smem + OFF_XS;
    float* pmax   = smem + OFF_PMAX;
    float* gate_s = smem + OFF_GATE;
    float* red    = smem + OFF_RED;
    float* bc     = smem + OFF_BC;
    float* mbox   = smem + OFF_MBOX;

    cg::cluster_group cluster = cg::this_cluster();
    const int rank = (int)cluster.block_rank();
    const int b    = blockIdx.x / CLUSTER;     // batch
    const int t    = threadIdx.x;
    const int lane = t & 31;
    const int wid  = t >> 5;                   // 8 warps

    const float* xb = x   + (size_t)b * (H * N) + rank * NCH;
    float*       ob = out + (size_t)b * (H * N) + rank * NCH;

    const int c4 = (t & 63) * 4;   // column group within chunk (0..252)
    const int h0 = t >> 6;         // 0..3

    // ---- Phase A: GMEM -> SMEM, partial max over this thread's 16 rows ----
    float4 pm = make_float4(-INFINITY, -INFINITY, -INFINITY, -INFINITY);
    #pragma unroll
    for (int it = 0; it < 16; ++it) {
        const int h = h0 + it * 4;
        float4 v = *reinterpret_cast<const float4*>(xb + (size_t)h * N + c4);
        *reinterpret_cast<float4*>(x_s + h * NCH + c4) = v;
        pm.x = fmaxf(pm.x, v.x);
        pm.y = fmaxf(pm.y, v.y);
        pm.z = fmaxf(pm.z, v.z);
        pm.w = fmaxf(pm.w, v.w);
    }
    *reinterpret_cast<float4*>(pmax + h0 * NCH + c4) = pm;
    __syncthreads();

    // ---- per-column max: thread t owns column t of the chunk ----
    float xm = fmaxf(fmaxf(pmax[0 * NCH + t], pmax[1 * NCH + t]),
                     fmaxf(pmax[2 * NCH + t], pmax[3 * NCH + t]));

    // ---- CTA max reduce (256 -> 1), then cluster max via mailbox ----
    float v = xm;
    #pragma unroll
    for (int o = 16; o > 0; o >>= 1)
        v = fmaxf(v, __shfl_xor_sync(0xffffffffu, v, o));
    if (lane == 0) red[wid] = v;
    __syncthreads();
    if (t == 0) {
        float m = red[0];
        #pragma unroll
        for (int w = 1; w < 8; ++w) m = fmaxf(m, red[w]);
        mbox[0] = m;
    }
    cluster.sync();
    if (t == 0) {
        float g = -INFINITY;
        #pragma unroll
        for (int r = 0; r < CLUSTER; ++r) {
            const float* p = (const float*)cluster.map_shared_rank((void*)mbox, r);
            g = fmaxf(g, p[0]);
        }
        bc[0] = g;
    }
    __syncthreads();
    const float gmax = bc[0];

    // ---- exp + CTA sum, then cluster sum via mailbox ----
    const float e = expf(xm - gmax);
    float s = e;
    #pragma unroll
    for (int o = 16; o > 0; o >>= 1)
        s += __shfl_xor_sync(0xffffffffu, s, o);
    if (lane == 0) red[wid] = s;
    __syncthreads();
    if (t == 0) {
        float m = red[0];
        #pragma unroll
        for (int w = 1; w < 8; ++w) m += red[w];
        mbox[1] = m;
    }
    cluster.sync();
    if (t == 0) {
        float tot = 0.0f;
        #pragma unroll
        for (int r = 0; r < CLUSTER; ++r) {
            const float* p = (const float*)cluster.map_shared_rank((void*)mbox, r);
            tot += p[1];
        }
        bc[1] = tot;
    }
    __syncthreads();
    const float inv = 1.0f / bc[1];

    gate_s[t] = e * inv;
    __syncthreads();

    // ---- Phase B: SMEM -> scale -> GMEM (streaming stores) ----
    const float4 g4 = *reinterpret_cast<const float4*>(gate_s + c4);
    #pragma unroll
    for (int it = 0; it < 16; ++it) {
        const int h = h0 + it * 4;
        float4 v2 = *reinterpret_cast<const float4*>(x_s + h * NCH + c4);
        v2.x *= g4.x; v2.y *= g4.y; v2.z *= g4.z; v2.w *= g4.w;
        __stcs(reinterpret_cast<float4*>(ob + (size_t)h * N + c4), v2);
    }

    // ---- DSMEM lifetime guard: no CTA exits while peers may still read its
    //      mailbox (the reads after the 2nd sync above). ----
    cluster.sync();
}

extern "C" void kernel_launch(void* const* d_in, const int* in_sizes, int n_in,
                              void* d_out, int out_size) {
    const float* x = (const float*)d_in[0];
    float* out = (float*)d_out;

    cudaFuncSetAttribute(fused_cluster_kernel,
                         cudaFuncAttributeMaxDynamicSharedMemorySize, SMEM_BYTES);
    fused_cluster_kernel<<<B * CLUSTER, THREADS, SMEM_BYTES>>>(x, out);
}

// round 6
// speedup vs baseline: 1.1373x; 1.0357x over previous
#include <cuda_runtime.h>
#include <math.h>

// x [256, 64, 2048] fp32.
//   xm   = max(x, axis=1); gate = softmax(xm, -1)   (SSA groups=1 == identity)
//   out  = gate[:, None, :] * x
//
// 3 decoupled launches, L2 reuse via reverse-order second pass:
//   K1a: partial max over h, 2048 balanced CTAs, pure read stream -> xm (2MB)
//   K1b: softmax(xm) in place (tiny)
//   K2 : out = gate * x, REVERSE block order so x reads hit the L2 lines K1a
//        just filled (LRU-friendly), __stcs stores to avoid write pollution.

#define B  256
#define H  64
#define N  2048
#define TILE 256                 // columns per K1a CTA
#define TPB  256

__device__ float g_xm[B * N];    // xm, overwritten in-place with gate (2 MB)

// ---- K1a: xm[b, tile] = max over h of x[b, :, tile] ----
__global__ __launch_bounds__(TPB)
void max_kernel(const float* __restrict__ x, float* __restrict__ xm) {
    __shared__ float pmax[4 * TILE];

    const int tileId = blockIdx.x;           // 0..2047
    const int b      = tileId >> 3;          // batch
    const int c0     = (tileId & 7) * TILE;  // column tile base
    const int t      = threadIdx.x;

    const float* xb = x + (size_t)b * (H * N) + c0;
    const int c4 = (t & 63) * 4;             // col group in tile
    const int h0 = t >> 6;                   // row-group 0..3

    float4 pm = make_float4(-INFINITY, -INFINITY, -INFINITY, -INFINITY);
    #pragma unroll
    for (int it = 0; it < 16; ++it) {
        const int h = h0 + it * 4;
        float4 v = *reinterpret_cast<const float4*>(xb + (size_t)h * N + c4);
        pm.x = fmaxf(pm.x, v.x);
        pm.y = fmaxf(pm.y, v.y);
        pm.z = fmaxf(pm.z, v.z);
        pm.w = fmaxf(pm.w, v.w);
    }
    *reinterpret_cast<float4*>(pmax + h0 * TILE + c4) = pm;
    __syncthreads();

    // thread t reduces column t of the tile
    float m = fmaxf(fmaxf(pmax[0 * TILE + t], pmax[1 * TILE + t]),
                    fmaxf(pmax[2 * TILE + t], pmax[3 * TILE + t]));
    xm[(size_t)b * N + c0 + t] = m;
}

// ---- K1b: gate = softmax(xm) rowwise, in place ----
__global__ __launch_bounds__(512)
void softmax_kernel(float* __restrict__ xm) {
    const int b    = blockIdx.x;
    const int t    = threadIdx.x;       // 512, each owns 4 cols
    const int lane = t & 31;
    const int wid  = t >> 5;

    float* row = xm + (size_t)b * N;
    float4 v = *reinterpret_cast<float4*>(row + t * 4);

    __shared__ float sred[16];
    __shared__ float s_gmax, s_gsum;

    float tm = fmaxf(fmaxf(v.x, v.y), fmaxf(v.z, v.w));
    #pragma unroll
    for (int o = 16; o > 0; o >>= 1)
        tm = fmaxf(tm, __shfl_xor_sync(0xffffffffu, tm, o));
    if (lane == 0) sred[wid] = tm;
    __syncthreads();
    if (wid == 0) {
        float m = (lane < 16) ? sred[lane] : -INFINITY;
        #pragma unroll
        for (int o = 8; o > 0; o >>= 1)
            m = fmaxf(m, __shfl_xor_sync(0xffffffffu, m, o));
        if (lane == 0) s_gmax = m;
    }
    __syncthreads();
    const float gmax = s_gmax;

    float4 e;
    e.x = expf(v.x - gmax);
    e.y = expf(v.y - gmax);
    e.z = expf(v.z - gmax);
    e.w = expf(v.w - gmax);
    float ts = (e.x + e.y) + (e.z + e.w);
    #pragma unroll
    for (int o = 16; o > 0; o >>= 1)
        ts += __shfl_xor_sync(0xffffffffu, ts, o);
    if (lane == 0) sred[wid] = ts;
    __syncthreads();
    if (wid == 0) {
        float m = (lane < 16) ? sred[lane] : 0.0f;
        #pragma unroll
        for (int o = 8; o > 0; o >>= 1)
            m += __shfl_xor_sync(0xffffffffu, m, o);
        if (lane == 0) s_gsum = m;
    }
    __syncthreads();
    const float inv = 1.0f / s_gsum;

    float4 g = make_float4(e.x * inv, e.y * inv, e.z * inv, e.w * inv);
    *reinterpret_cast<float4*>(row + t * 4) = g;
}

// ---- K2: out = gate * x, reverse block order for L2 reuse ----
#define K2_BLOCKS 32768
__global__ __launch_bounds__(256)
void scale_kernel(const float* __restrict__ x, const float* __restrict__ gate,
                  float* __restrict__ out) {
    const long long rb = (long long)(K2_BLOCKS - 1 - blockIdx.x);
    const long long i4 = rb * blockDim.x + threadIdx.x;
    const long long e  = i4 << 2;               // element index
    const long long b  = e >> 17;               // / (64*2048)
    const int       n  = (int)(e & (N - 1));

    float4 v = __ldcs(reinterpret_cast<const float4*>(x + e));
    float4 g = *reinterpret_cast<const float4*>(gate + (b << 11) + n);
    v.x *= g.x; v.y *= g.y; v.z *= g.z; v.w *= g.w;
    __stcs(reinterpret_cast<float4*>(out + e), v);
}

extern "C" void kernel_launch(void* const* d_in, const int* in_sizes, int n_in,
                              void* d_out, int out_size) {
    const float* x = (const float*)d_in[0];
    float* out = (float*)d_out;

    float* xm;
    cudaGetSymbolAddress((void**)&xm, g_xm);

    max_kernel<<<B * (N / TILE), TPB>>>(x, xm);      // 2048 CTAs
    softmax_kernel<<<B, 512>>>(xm);                  // 256 CTAs (tiny)
    scale_kernel<<<K2_BLOCKS, 256>>>(x, xm, out);    // reversed order
}